// round 10
// baseline (speedup 1.0000x reference)
#include <cuda_runtime.h>
#include <cstdint>

// Problem constants (fixed by the reference)
#define BB 8
#define TT 512
#define DD 512
#define D4 (DD / 4)       // 128 float4 per frame
#define MAX_LEN 7680      // TT * 15
#define PH 4              // phonemes per CTA (one per 128-lane group)
#define NSEG (TT / PH)    // 128 CTAs per batch
#define ZSLICE (MAX_LEN / NSEG)  // 60 tail frames owned per CTA

// ---------------------------------------------------------------------------
// Single fused kernel, phoneme-centric. Grid (128, 8), block 512.
//   Phase 1: shfl block-scan of max(dur,1) into SMEM cum (2 barriers).
//   Phase 2: group g (128 lanes) owns phoneme t = seg*4+g. Loads its frame
//            ONCE (1 float4/lane) and stores it to frames [cum[t-1], cum[t])
//            — contiguous, coalesced 2 KB stores, no per-repeat reload.
//   Phase 3: tail zeros — CTA's 60-frame slice ∩ [total, MAX_LEN), stored
//            from registers (zero loads).
// ---------------------------------------------------------------------------
__global__ void __launch_bounds__(512) fused_expand_kernel(
    const float4* __restrict__ feat,  // (B, T, D/4)
    const int*    __restrict__ dur,   // (B, T)
    float4*       __restrict__ out)   // (B, MAX_LEN, D/4)
{
    __shared__ int cum[TT];
    __shared__ int wsum[16];

    const int b   = blockIdx.y;
    const int seg = blockIdx.x;            // 0..NSEG-1
    const int tid = threadIdx.x;           // 0..511
    const int lane5 = tid & 31, w = tid >> 5;

    // ---- Phase 1: inclusive scan of clamped durations ----
    int v = __ldg(&dur[b * TT + tid]);
    v = (v < 1) ? 1 : v;
    int x = v;
#pragma unroll
    for (int o = 1; o < 32; o <<= 1) {
        int y = __shfl_up_sync(0xFFFFFFFFu, x, o);
        if (lane5 >= o) x += y;
    }
    if (lane5 == 31) wsum[w] = x;
    __syncthreads();
    if (w == 0) {
        int s = (lane5 < 16) ? wsum[lane5] : 0;
#pragma unroll
        for (int o = 1; o < 16; o <<= 1) {
            int y = __shfl_up_sync(0xFFFFFFFFu, s, o);
            if (lane5 >= o) s += y;
        }
        if (lane5 < 16) wsum[lane5] = s;
    }
    __syncthreads();
    cum[tid] = ((w > 0) ? wsum[w - 1] : 0) + x;
    __syncthreads();

    const int total = cum[TT - 1];
    const int g    = tid >> 7;     // 0..3  (group = phoneme slot)
    const int lane = tid & 127;    // 0..127

    // ---- Phase 2: load frame once, store dur times ----
    const int t     = seg * PH + g;
    const int end   = cum[t];                       // LDS broadcast per group
    const int start = (t > 0) ? cum[t - 1] : 0;

    const float4 val = __ldg(feat + ((size_t)b * TT + t) * D4 + lane);

    float4* ob = out + ((size_t)b * MAX_LEN + start) * D4 + lane;
    for (int r = start; r < end; r++, ob += D4)
        __stcs(ob, val);                            // streaming store

    // ---- Phase 3: tail zeros (group-strided over this CTA's slice) ----
    const int zlo = seg * ZSLICE;
    const int zhi = zlo + ZSLICE;
    const float4 zero = make_float4(0.f, 0.f, 0.f, 0.f);
    for (int n = zlo + g; n < zhi; n += PH) {
        if (n >= total)
            __stcs(out + ((size_t)b * MAX_LEN + n) * D4 + lane, zero);
    }
}

// ---------------------------------------------------------------------------
// Launch
// ---------------------------------------------------------------------------
extern "C" void kernel_launch(void* const* d_in, const int* in_sizes, int n_in,
                              void* d_out, int out_size) {
    const float4* feat = (const float4*)d_in[0];  // features (8,512,512) f32
    const int*    dur  = (const int*)d_in[1];     // durations (8,512) i32
    float4*       out  = (float4*)d_out;          // (8,7680,512) f32

    (void)in_sizes; (void)n_in; (void)out_size;

    dim3 grid(NSEG, BB, 1);
    fused_expand_kernel<<<grid, 512>>>(feat, dur, out);
}

// round 11
// speedup vs baseline: 1.0987x; 1.0987x over previous
#include <cuda_runtime.h>
#include <cstdint>

// Problem constants (fixed by the reference)
#define BB 8
#define TT 512
#define DD 512
#define D4 (DD / 4)       // 128 float4 per frame
#define FRAME_BYTES (DD * 4)
#define MAX_LEN 7680      // TT * 15
#define FR 32             // output frames per CTA
#define ZCHUNK_FRAMES 8   // frames per bulk zero op (16 KB)
#define ZBUF_BYTES (ZCHUNK_FRAMES * FRAME_BYTES)   // 16 KB

// ---------------------------------------------------------------------------
// Single fused kernel. Grid (240, 8), block 512.
//   Phase 0: zero-fill 16 KB SMEM staging buffer (ordered by scan barriers).
//   Phase 1: shfl block-scan of max(dur,1); thread t keeps [start,end).
//   Phase 2: scatter t into sidx for owned frames inside the CTA window.
//   Phase 3a: frames >= total in this window -> up to 4 threads each issue
//             one 16 KB cp.async.bulk zero store (LSU-free, parallel issue).
//   Phase 3b: valid frames -> R9 gather: (128 lanes x 4) x (2 waves x 4),
//             float4 loads + streaming stores; invalid frames skipped.
//   End: bulk waits (overlapped with the gather work above).
// ---------------------------------------------------------------------------
__global__ void __launch_bounds__(512) fused_expand_kernel(
    const float4* __restrict__ feat,  // (B, T, D/4)
    const int*    __restrict__ dur,   // (B, T)
    float4*       __restrict__ out)   // (B, MAX_LEN, D/4)
{
    __shared__ alignas(128) float4 szero[ZBUF_BYTES / 16];  // 16 KB of zeros
    __shared__ int wsum[16];
    __shared__ int sidx[FR];

    const int b     = blockIdx.y;
    const int base0 = blockIdx.x * FR;
    const int tid   = threadIdx.x;          // 0..511
    const int lane5 = tid & 31, w = tid >> 5;

    // ---- Phase 0: zero staging buffer + sidx pre-init ----
    const float4 zero = make_float4(0.f, 0.f, 0.f, 0.f);
#pragma unroll
    for (int i = 0; i < (ZBUF_BYTES / 16) / 512; i++)
        szero[tid + 512 * i] = zero;
    if (tid < FR) sidx[tid] = -1;

    // ---- Phase 1: inclusive scan of clamped durations ----
    int v = __ldg(&dur[b * TT + tid]);
    v = (v < 1) ? 1 : v;
    int x = v;
#pragma unroll
    for (int o = 1; o < 32; o <<= 1) {
        int y = __shfl_up_sync(0xFFFFFFFFu, x, o);
        if (lane5 >= o) x += y;
    }
    if (lane5 == 31) wsum[w] = x;
    __syncthreads();
    if (w == 0) {
        int s = (lane5 < 16) ? wsum[lane5] : 0;
#pragma unroll
        for (int o = 1; o < 16; o <<= 1) {
            int y = __shfl_up_sync(0xFFFFFFFFu, s, o);
            if (lane5 >= o) s += y;
        }
        if (lane5 < 16) wsum[lane5] = s;
    }
    __syncthreads();
    const int end   = ((w > 0) ? wsum[w - 1] : 0) + x;  // inclusive cumsum
    const int start = end - v;
    const int total = __shfl_sync(0xFFFFFFFFu,
                                  (w == 15) ? end : 0, 31) ;  // placeholder, fixed below

    // total = cum[TT-1]: broadcast via SMEM (wsum[15] holds full sum).
    const int total_all = wsum[15];

    // ---- Phase 2: scatter phoneme id into this CTA's frame window ----
    {
        int lo = (start > base0) ? start : base0;
        const int hi = (end < base0 + FR) ? end : (base0 + FR);
        for (int i = lo; i < hi; i++) sidx[i - base0] = tid;
    }
    __syncthreads();

    // ---- Phase 3a: bulk zero stores for the invalid sub-window ----
    int nvalid = total_all - base0;
    nvalid = (nvalid < 0) ? 0 : (nvalid > FR ? FR : nvalid);
    const int zframes = FR - nvalid;
    bool issued = false;
    if (zframes > 0 && tid < 4 && tid * ZCHUNK_FRAMES < zframes) {
        // Generic-proxy SMEM zero writes -> async-proxy read ordering.
        asm volatile("fence.proxy.async.shared::cta;" ::: "memory");
        const int f0 = nvalid + tid * ZCHUNK_FRAMES;
        int nf = zframes - tid * ZCHUNK_FRAMES;
        if (nf > ZCHUNK_FRAMES) nf = ZCHUNK_FRAMES;
        const uint32_t s_z = (uint32_t)__cvta_generic_to_shared(szero);
        char* g = (char*)out + ((size_t)b * MAX_LEN + base0 + f0) * FRAME_BYTES;
        const uint32_t nbytes = (uint32_t)nf * FRAME_BYTES;
        asm volatile(
            "cp.async.bulk.global.shared::cta.bulk_group [%0], [%1], %2;"
            :: "l"(g), "r"(s_z), "r"(nbytes) : "memory");
        asm volatile("cp.async.bulk.commit_group;" ::: "memory");
        issued = true;
    }

    // ---- Phase 3b: gather-expand for valid frames (two 16-frame waves) ----
    const int y    = tid >> 7;   // 0..3
    const int lane = tid & 127;  // 0..127
    const float4* __restrict__ fb = feat + (size_t)b * TT * D4;

#pragma unroll
    for (int half = 0; half < 2; half++) {
        const int fbase = base0 + 16 * half + y;
        float4* __restrict__ ob =
            out + ((size_t)b * MAX_LEN + fbase) * D4 + lane;

        int idx[4];
#pragma unroll
        for (int j = 0; j < 4; j++)
            idx[j] = sidx[16 * half + y + 4 * j];     // SMEM broadcast

        float4 val[4];
#pragma unroll
        for (int j = 0; j < 4; j++)
            if (idx[j] >= 0)
                val[j] = __ldg(fb + (size_t)idx[j] * D4 + lane);
#pragma unroll
        for (int j = 0; j < 4; j++)
            if (idx[j] >= 0)
                __stcs(&ob[(size_t)4 * j * D4], val[j]);  // streaming store
    }

    // ---- Drain bulk zero stores (overlapped with gather above) ----
    if (issued)
        asm volatile("cp.async.bulk.wait_group 0;" ::: "memory");
}

// ---------------------------------------------------------------------------
// Launch
// ---------------------------------------------------------------------------
extern "C" void kernel_launch(void* const* d_in, const int* in_sizes, int n_in,
                              void* d_out, int out_size) {
    const float4* feat = (const float4*)d_in[0];  // features (8,512,512) f32
    const int*    dur  = (const int*)d_in[1];     // durations (8,512) i32
    float4*       out  = (float4*)d_out;          // (8,7680,512) f32

    (void)in_sizes; (void)n_in; (void)out_size;

    dim3 grid(MAX_LEN / FR, BB, 1);
    fused_expand_kernel<<<grid, 512>>>(feat, dur, out);
}